// round 16
// baseline (speedup 1.0000x reference)
#include <cuda_runtime.h>
#include <cstdint>

// Problem constants (fixed shapes per reference)
#define BB    256
#define VV    128000
#define LL    32
#define NNEG  1024
#define EPSF  1e-8f
#define TMARG 2.0f
#define NTHR  0.1f

// Flattened quad-work decomposition (1 quad = one int4 of ids = 4 gathers):
//   neg : 256 rows * 256 quads = 65536   (gt in [0, 65536))
//   ko  : 256 rows *   8 quads =  2048   (gt in [65536, 67584))
//   en  : 256 rows *   8 quads =  2048   (gt in [67584, 69632))
// grid = 592 CTAs (= 4 * 148, one perfect wave) * 128 threads.
// Class boundaries are multiples of 128 -> every CTA is single-class.
#define GRID   592
#define NTHRD  128
#define Q_NEG  65536
#define Q_KO   67584
#define Q_EN   69632

// Deterministic scratch: per-CTA partials [self, target, margin, neg_sum]
__device__ float        g_partial[GRID * 4];
__device__ unsigned int g_count = 0;   // reset by last block -> graph-replay-safe

__global__ __launch_bounds__(NTHRD) void fused_kernel(
    const float* __restrict__ sparse,
    const int*   __restrict__ ko_ids,
    const int*   __restrict__ ko_len,
    const int*   __restrict__ en_ids,
    const int*   __restrict__ en_len,
    const int*   __restrict__ neg_ids,
    float*       __restrict__ out)
{
    const int t  = threadIdx.x;
    const int gt = blockIdx.x * NTHRD + t;

    float v_self = 0.0f, v_tgt = 0.0f, v_mar = 0.0f, v_neg = 0.0f;

    if (gt < Q_NEG) {
        // ---- negatives: broadcast-group gather ----
        // A warp covers 128 ids (32 quads) as before, but restructured so each
        // LDG touches only 8 DISTINCT lines, each address shared by a 4-lane
        // group (L1tex coalescer dedups to 8 wavefronts). Same total
        // wavefronts, but cross-LDG (1.0 cyc/wf) instead of within-LDG
        // replays (2.07 cyc/wf). Lane accumulates only its own element
        // (e == element index) -> each id counted exactly once, deterministic.
        const int lane = t & 31;
        const int g    = lane >> 2;           // 4-lane group 0..7
        const int e    = lane & 3;            // element within quad
        const int b    = gt >> 8;             // row (uniform per warp)
        const int q0   = (gt & 255) & ~31;    // warp's first quad in the row
        const float* __restrict__ row = sparse + (size_t)b * VV;
        const int4* __restrict__ nq = reinterpret_cast<const int4*>(neg_ids);

        float acc = 0.0f;
        #pragma unroll
        for (int p = 0; p < 4; p++) {
            const int4 ids = nq[q0 + p * 8 + g];   // group-uniform int4
            const float x0 = __ldg(row + ids.x);   // 8 distinct lines/LDG
            const float x1 = __ldg(row + ids.y);
            const float x2 = __ldg(row + ids.z);
            const float x3 = __ldg(row + ids.w);
            float r;
            if      (e == 0) r = x0;
            else if (e == 1) r = x1;
            else if (e == 2) r = x2;
            else             r = x3;
            acc += fmaxf(r - NTHR, 0.0f);
        }
        v_neg = acc;
    } else if (gt < Q_KO) {
        // ---- ko quad: row b, quad j (elements j*4 .. j*4+3 of 32) ----
        const int q = gt - Q_NEG;
        const int b = q >> 3;
        const int j = q & 7;
        const int kl = ko_len[b];
        const float* __restrict__ row = sparse + (size_t)b * VV;
        const int4 ids = reinterpret_cast<const int4*>(ko_ids)[b * 8 + j];
        const int e0 = j * 4;
        const float a0 = __ldg(row + ids.x);
        const float a1 = __ldg(row + ids.y);
        const float a2 = __ldg(row + ids.z);
        const float a3 = __ldg(row + ids.w);
        float s = 0.0f;
        if (e0 + 0 < kl) s -= __logf(a0 + EPSF);
        if (e0 + 1 < kl) s -= __logf(a1 + EPSF);
        if (e0 + 2 < kl) s -= __logf(a2 + EPSF);
        if (e0 + 3 < kl) s -= __logf(a3 + EPSF);
        // masked_mean: kl==0 -> s==0, so s/max(kl,1)==0 matches jnp.where.
        v_self = s / fmaxf((float)kl, 1.0f);
    } else if (gt < Q_EN) {
        // ---- en quad: -log + margin terms ----
        const int q = gt - Q_KO;
        const int b = q >> 3;
        const int j = q & 7;
        const int el = en_len[b];
        const float* __restrict__ row = sparse + (size_t)b * VV;
        const int4 ids = reinterpret_cast<const int4*>(en_ids)[b * 8 + j];
        const int e0 = j * 4;
        const float a0 = __ldg(row + ids.x);
        const float a1 = __ldg(row + ids.y);
        const float a2 = __ldg(row + ids.z);
        const float a3 = __ldg(row + ids.w);
        float st = 0.0f, sm = 0.0f;
        if (e0 + 0 < el) { st -= __logf(a0 + EPSF); sm += fmaxf(TMARG - a0, 0.0f); }
        if (e0 + 1 < el) { st -= __logf(a1 + EPSF); sm += fmaxf(TMARG - a1, 0.0f); }
        if (e0 + 2 < el) { st -= __logf(a2 + EPSF); sm += fmaxf(TMARG - a2, 0.0f); }
        if (e0 + 3 < el) { st -= __logf(a3 + EPSF); sm += fmaxf(TMARG - a3, 0.0f); }
        const float ce = fmaxf((float)el, 1.0f);
        v_tgt = st / ce;
        v_mar = sm / ce;
    }
    // gt >= Q_EN: idle CTA, zero partials

    // ---- warp reduction (fixed shuffle order -> deterministic) ----
    #pragma unroll
    for (int off = 16; off > 0; off >>= 1) {
        v_self += __shfl_down_sync(0xFFFFFFFFu, v_self, off);
        v_tgt  += __shfl_down_sync(0xFFFFFFFFu, v_tgt,  off);
        v_mar  += __shfl_down_sync(0xFFFFFFFFu, v_mar,  off);
        v_neg  += __shfl_down_sync(0xFFFFFFFFu, v_neg,  off);
    }

    __shared__ float sh[4][4];       // 128 threads = 4 warps
    const int wid = t >> 5;
    if ((t & 31) == 0) {
        sh[wid][0] = v_self;
        sh[wid][1] = v_tgt;
        sh[wid][2] = v_mar;
        sh[wid][3] = v_neg;
    }
    __syncthreads();

    __shared__ bool s_last;
    if (t == 0) {
        float s0 = 0.f, s1 = 0.f, s2 = 0.f, s3 = 0.f;
        #pragma unroll
        for (int w = 0; w < 4; w++) {
            s0 += sh[w][0]; s1 += sh[w][1]; s2 += sh[w][2]; s3 += sh[w][3];
        }
        const int blk = blockIdx.x;
        g_partial[blk * 4 + 0] = s0;
        g_partial[blk * 4 + 1] = s1;
        g_partial[blk * 4 + 2] = s2;
        g_partial[blk * 4 + 3] = s3;
        __threadfence();
        const unsigned int ticket = atomicAdd(&g_count, 1u);
        s_last = (ticket == GRID - 1);
    }
    __syncthreads();

    if (!s_last) return;

    // ---- last block: one-pass final reduce, warp w handles component w ----
    __threadfence();  // acquire all g_partial writes
    {
        const int k    = wid;        // 4 warps, 4 components
        const int lane = t & 31;
        float s = 0.0f;
        #pragma unroll
        for (int i = 0; i < 19; i++) {           // 19*32 = 608 >= 592
            const int p = i * 32 + lane;
            if (p < GRID) s += g_partial[p * 4 + k];
        }
        #pragma unroll
        for (int off = 16; off > 0; off >>= 1)
            s += __shfl_down_sync(0xFFFFFFFFu, s, off);

        if (lane == 0) {
            out[k] = (k < 3) ? (s / (float)BB)
                             : (s / (float)(BB * NNEG));
        }
        if (t == 0) g_count = 0;   // reset for next graph replay
    }
}

extern "C" void kernel_launch(void* const* d_in, const int* in_sizes, int n_in,
                              void* d_out, int out_size)
{
    const float* sparse  = (const float*)d_in[0];
    const int*   ko_ids  = (const int*)d_in[1];
    const int*   ko_len  = (const int*)d_in[2];
    const int*   en_ids  = (const int*)d_in[3];
    const int*   en_len  = (const int*)d_in[4];
    const int*   neg_ids = (const int*)d_in[5];
    float* out = (float*)d_out;

    fused_kernel<<<GRID, NTHRD>>>(sparse, ko_ids, ko_len, en_ids, en_len,
                                  neg_ids, out);
}

// round 17
// speedup vs baseline: 1.2000x; 1.2000x over previous
#include <cuda_runtime.h>
#include <cstdint>

// Problem constants (fixed shapes per reference)
#define BB    256
#define VV    128000
#define LL    32
#define NNEG  1024
#define EPSF  1e-8f
#define TMARG 2.0f
#define NTHR  0.1f

// Element-flat work decomposition (perfect per-SM balance):
//   neg : 256 rows * 1024      = 262144   elements  [0, 262144)
//   ko  : 256 rows * 32        =   8192             [262144, 270336)
//   en  : 256 rows * 32        =   8192             [270336, 278528)
// grid = 592 CTAs (= 4 * 148, one exact wave) * 128 thr = 75776 threads.
// Thread gt handles elements e = gt + k*75776, k = 0..3  (3 or 4 each;
// the 4-element/3-element boundary gt=51200 is warp-aligned).
#define GRID    592
#define NTHRD   128
#define TTOT    75776
#define E_NEG   262144
#define E_KO    270336
#define E_TOT   278528

// Deterministic scratch: per-CTA partials [self, target, margin, neg_sum]
__device__ float        g_partial[GRID * 4];
__device__ unsigned int g_count = 0;   // reset by last block -> graph-replay-safe

__global__ __launch_bounds__(NTHRD) void fused_kernel(
    const float* __restrict__ sparse,
    const int*   __restrict__ ko_ids,
    const int*   __restrict__ ko_len,
    const int*   __restrict__ en_ids,
    const int*   __restrict__ en_len,
    const int*   __restrict__ neg_ids,
    float*       __restrict__ out)
{
    const int t  = threadIdx.x;
    const int gt = blockIdx.x * NTHRD + t;

    float v_self = 0.0f, v_tgt = 0.0f, v_mar = 0.0f, v_neg = 0.0f;

    #pragma unroll
    for (int k = 0; k < 4; k++) {
        const int e = gt + k * TTOT;
        if (e >= E_TOT) break;

        if (e < E_NEG) {
            // ---- negative element: row b, id j (index load coalesced) ----
            const int b = e >> 10;
            const int j = e & 1023;
            const int id = __ldg(neg_ids + j);
            const float x = __ldg(sparse + (size_t)b * VV + id);
            v_neg += fmaxf(x - NTHR, 0.0f);
        } else if (e < E_KO) {
            // ---- ko element: row b, position pos of 32 ----
            const int q   = e - E_NEG;
            const int b   = q >> 5;
            const int pos = q & 31;
            const int kl  = ko_len[b];
            if (pos < kl) {                  // skip masked loads entirely
                const int id = __ldg(ko_ids + b * LL + pos);
                const float a = __ldg(sparse + (size_t)b * VV + id);
                // per-element masked-mean scaling (kl > 0 here)
                v_self += -__logf(a + EPSF) / (float)kl;
            }
        } else {
            // ---- en element: -log + margin terms ----
            const int q   = e - E_KO;
            const int b   = q >> 5;
            const int pos = q & 31;
            const int el  = en_len[b];
            if (pos < el) {
                const int id = __ldg(en_ids + b * LL + pos);
                const float a = __ldg(sparse + (size_t)b * VV + id);
                const float ce = (float)el;
                v_tgt += -__logf(a + EPSF) / ce;
                v_mar += fmaxf(TMARG - a, 0.0f) / ce;
            }
        }
    }

    // ---- warp reduction (fixed shuffle order -> deterministic) ----
    #pragma unroll
    for (int off = 16; off > 0; off >>= 1) {
        v_self += __shfl_down_sync(0xFFFFFFFFu, v_self, off);
        v_tgt  += __shfl_down_sync(0xFFFFFFFFu, v_tgt,  off);
        v_mar  += __shfl_down_sync(0xFFFFFFFFu, v_mar,  off);
        v_neg  += __shfl_down_sync(0xFFFFFFFFu, v_neg,  off);
    }

    __shared__ float sh[4][4];       // 128 threads = 4 warps
    const int wid = t >> 5;
    if ((t & 31) == 0) {
        sh[wid][0] = v_self;
        sh[wid][1] = v_tgt;
        sh[wid][2] = v_mar;
        sh[wid][3] = v_neg;
    }
    __syncthreads();

    __shared__ bool s_last;
    if (t == 0) {
        float s0 = 0.f, s1 = 0.f, s2 = 0.f, s3 = 0.f;
        #pragma unroll
        for (int w = 0; w < 4; w++) {
            s0 += sh[w][0]; s1 += sh[w][1]; s2 += sh[w][2]; s3 += sh[w][3];
        }
        const int blk = blockIdx.x;
        g_partial[blk * 4 + 0] = s0;
        g_partial[blk * 4 + 1] = s1;
        g_partial[blk * 4 + 2] = s2;
        g_partial[blk * 4 + 3] = s3;
        __threadfence();
        const unsigned int ticket = atomicAdd(&g_count, 1u);
        s_last = (ticket == GRID - 1);
    }
    __syncthreads();

    if (!s_last) return;

    // ---- last block: one-pass final reduce, warp w handles component w ----
    __threadfence();  // acquire all g_partial writes
    {
        const int k    = wid;        // 4 warps, 4 components
        const int lane = t & 31;
        float s = 0.0f;
        #pragma unroll
        for (int i = 0; i < 19; i++) {           // 19*32 = 608 >= 592
            const int p = i * 32 + lane;
            if (p < GRID) s += g_partial[p * 4 + k];
        }
        #pragma unroll
        for (int off = 16; off > 0; off >>= 1)
            s += __shfl_down_sync(0xFFFFFFFFu, s, off);

        if (lane == 0) {
            out[k] = (k < 3) ? (s / (float)BB)
                             : (s / (float)(BB * NNEG));
        }
        if (t == 0) g_count = 0;   // reset for next graph replay
    }
}

extern "C" void kernel_launch(void* const* d_in, const int* in_sizes, int n_in,
                              void* d_out, int out_size)
{
    const float* sparse  = (const float*)d_in[0];
    const int*   ko_ids  = (const int*)d_in[1];
    const int*   ko_len  = (const int*)d_in[2];
    const int*   en_ids  = (const int*)d_in[3];
    const int*   en_len  = (const int*)d_in[4];
    const int*   neg_ids = (const int*)d_in[5];
    float* out = (float*)d_out;

    fused_kernel<<<GRID, NTHRD>>>(sparse, ko_ids, ko_len, en_ids, en_len,
                                  neg_ids, out);
}